// round 3
// baseline (speedup 1.0000x reference)
#include <cuda_runtime.h>
#include <cuda_bf16.h>
#include <math.h>
#include <stdint.h>

#define NTOK 2048
#define VOCAB 32000
#define KSTU 1024
#define KTEA 2048
#define IGNORE_INDEX (-100)

// ---------------- scratch (device globals; no runtime allocation) -----------
__device__ __align__(16) __nv_bfloat16 g_SI[NTOK * KSTU];
__device__ __align__(16) __nv_bfloat16 g_TI[NTOK * KTEA];
__device__ __align__(16) __nv_bfloat16 g_SW[VOCAB * KSTU];
__device__ __align__(16) __nv_bfloat16 g_TW[(size_t)VOCAB * KTEA];
__device__ __align__(16) float g_LS[(size_t)NTOK * VOCAB];
__device__ __align__(16) float g_LT[(size_t)NTOK * VOCAB];
__device__ float g_lseS[NTOK];
__device__ float g_lseT[NTOK];
__device__ int g_tgt[NTOK];
__device__ double g_hard;
__device__ double g_skl;
__device__ double g_tkl;
__device__ int g_nvalid;

// ---------------- zero accumulators ----------------------------------------
__global__ void zero_acc_kernel() {
    g_hard = 0.0;
    g_skl = 0.0;
    g_tkl = 0.0;
    g_nvalid = 0;
}

// ---------------- target dtype detection + conversion -----------------------
// JAX silently downcasts int64->int32 without x64 mode, so the target buffer
// may be int32 (8KB) or int64 (16KB). Interpreting as int32 words: an int64
// little-endian layout has every odd word in {0,-1} (sign extension). Random
// targets in [0,32000) cannot satisfy that at all 1024 odd positions.
// We never read past 8KB unless int64 layout is confirmed.
__global__ __launch_bounds__(1024) void tgt_cvt_kernel(const int* __restrict__ raw) {
    __shared__ int s_all64;
    int tid = threadIdx.x;
    if (tid == 0) s_all64 = 1;
    __syncthreads();
    // Each of 1024 threads checks one odd word (within the first 8KB).
    int hw = raw[2 * tid + 1];
    if (hw != 0 && hw != -1) atomicAnd(&s_all64, 0);
    __syncthreads();
    int is64 = s_all64;
    // Convert 2048 targets; 2 per thread.
    for (int i = tid; i < NTOK; i += 1024) {
        g_tgt[i] = is64 ? raw[2 * i] : raw[i];
    }
}

// ---------------- fp32 -> bf16 convert (vectorized) ------------------------
__global__ void cvt_kernel(const float4* __restrict__ src, int which, int n4) {
    int i = blockIdx.x * blockDim.x + threadIdx.x;
    if (i >= n4) return;
    __nv_bfloat162* dst =
        which == 0 ? (__nv_bfloat162*)g_SI :
        which == 1 ? (__nv_bfloat162*)g_TI :
        which == 2 ? (__nv_bfloat162*)g_SW :
                     (__nv_bfloat162*)g_TW;
    float4 v = src[i];
    dst[2 * i + 0] = __floats2bfloat162_rn(v.x, v.y);
    dst[2 * i + 1] = __floats2bfloat162_rn(v.z, v.w);
}

// ---------------- bf16 tensor-core GEMM: C[n][v] = sum_k X[n][k] W[v][k] ----
__device__ __forceinline__ void mma16816(float c[4], const uint32_t a[4],
                                         const uint32_t b[2]) {
    asm("mma.sync.aligned.m16n8k16.row.col.f32.bf16.bf16.f32 "
        "{%0,%1,%2,%3},{%4,%5,%6,%7},{%8,%9},{%0,%1,%2,%3};"
        : "+f"(c[0]), "+f"(c[1]), "+f"(c[2]), "+f"(c[3])
        : "r"(a[0]), "r"(a[1]), "r"(a[2]), "r"(a[3]), "r"(b[0]), "r"(b[1]));
}

template <int WHICH>
__global__ __launch_bounds__(256) void gemm_kernel() {
    constexpr int K = (WHICH == 0) ? KSTU : KTEA;
    const __nv_bfloat16* __restrict__ A = (WHICH == 0) ? g_SI : g_TI;
    const __nv_bfloat16* __restrict__ B = (WHICH == 0) ? g_SW : g_TW;
    float* __restrict__ C = (WHICH == 0) ? g_LS : g_LT;

    constexpr int BM = 128, BN = 128, BK = 32;
    constexpr int LDS_T = BK + 8;  // padded row stride (elements), 80B

    __shared__ __align__(16) __nv_bfloat16 As[BM * LDS_T];
    __shared__ __align__(16) __nv_bfloat16 Bs[BN * LDS_T];

    const int m0 = blockIdx.y * BM;
    const int n0 = blockIdx.x * BN;
    const int tid = threadIdx.x;
    const int lane = tid & 31;
    const int wid = tid >> 5;
    const int warp_m = wid >> 2;   // 0..1
    const int warp_n = wid & 3;    // 0..3
    const int grp = lane >> 2;     // 0..7
    const int tq = lane & 3;       // 0..3

    float acc[4][4][4];
#pragma unroll
    for (int mi = 0; mi < 4; mi++)
#pragma unroll
        for (int ni = 0; ni < 4; ni++)
#pragma unroll
            for (int r = 0; r < 4; r++) acc[mi][ni][r] = 0.0f;

    for (int k0 = 0; k0 < K; k0 += BK) {
        // stage 128x32 tiles of A and B (2 rounds of uint4 per thread each)
#pragma unroll
        for (int r = 0; r < 2; r++) {
            int idx = tid * 8 + r * 2048;
            int row = idx >> 5;
            int col = idx & 31;
            *(uint4*)&As[row * LDS_T + col] =
                *(const uint4*)&A[(size_t)(m0 + row) * K + k0 + col];
            *(uint4*)&Bs[row * LDS_T + col] =
                *(const uint4*)&B[(size_t)(n0 + row) * K + k0 + col];
        }
        __syncthreads();

#pragma unroll
        for (int kk = 0; kk < 2; kk++) {
            const int kb = kk * 16;
            uint32_t a[4][4], b[4][2];
#pragma unroll
            for (int mi = 0; mi < 4; mi++) {
                int mrow = warp_m * 64 + mi * 16 + grp;
                a[mi][0] = *(const uint32_t*)&As[mrow * LDS_T + kb + tq * 2];
                a[mi][1] = *(const uint32_t*)&As[(mrow + 8) * LDS_T + kb + tq * 2];
                a[mi][2] = *(const uint32_t*)&As[mrow * LDS_T + kb + tq * 2 + 8];
                a[mi][3] = *(const uint32_t*)&As[(mrow + 8) * LDS_T + kb + tq * 2 + 8];
            }
#pragma unroll
            for (int ni = 0; ni < 4; ni++) {
                int nrow = warp_n * 32 + ni * 8 + grp;
                b[ni][0] = *(const uint32_t*)&Bs[nrow * LDS_T + kb + tq * 2];
                b[ni][1] = *(const uint32_t*)&Bs[nrow * LDS_T + kb + tq * 2 + 8];
            }
#pragma unroll
            for (int mi = 0; mi < 4; mi++)
#pragma unroll
                for (int ni = 0; ni < 4; ni++) mma16816(acc[mi][ni], a[mi], b[ni]);
        }
        __syncthreads();
    }

    // epilogue: fp32 logits to scratch
#pragma unroll
    for (int mi = 0; mi < 4; mi++) {
#pragma unroll
        for (int ni = 0; ni < 4; ni++) {
            int row = m0 + warp_m * 64 + mi * 16 + grp;
            int col = n0 + warp_n * 32 + ni * 8 + tq * 2;
            float2 v0 = make_float2(acc[mi][ni][0], acc[mi][ni][1]);
            float2 v1 = make_float2(acc[mi][ni][2], acc[mi][ni][3]);
            *(float2*)&C[(size_t)row * VOCAB + col] = v0;
            *(float2*)&C[(size_t)(row + 8) * VOCAB + col] = v1;
        }
    }
}

// ---------------- per-row logsumexp (student & teacher) + hard CE ----------
__global__ __launch_bounds__(256) void rowstats_kernel() {
    const int row = blockIdx.x;
    const float* __restrict__ s = g_LS + (size_t)row * VOCAB;
    const float* __restrict__ t = g_LT + (size_t)row * VOCAB;
    const int tid = threadIdx.x;

    float mS = -1e30f, sS = 0.0f, mT = -1e30f, sT = 0.0f;
    for (int v = tid; v < VOCAB; v += 256) {
        float xs = s[v];
        float xt = t[v];
        float nmS = fmaxf(mS, xs);
        sS = sS * __expf(mS - nmS) + __expf(xs - nmS);
        mS = nmS;
        float nmT = fmaxf(mT, xt);
        sT = sT * __expf(mT - nmT) + __expf(xt - nmT);
        mT = nmT;
    }

    __shared__ float shmS[256], shsS[256], shmT[256], shsT[256];
    shmS[tid] = mS; shsS[tid] = sS; shmT[tid] = mT; shsT[tid] = sT;
    __syncthreads();
    for (int off = 128; off > 0; off >>= 1) {
        if (tid < off) {
            float m1 = shmS[tid], s1 = shsS[tid];
            float m2 = shmS[tid + off], s2 = shsS[tid + off];
            float m = fmaxf(m1, m2);
            shsS[tid] = s1 * __expf(m1 - m) + s2 * __expf(m2 - m);
            shmS[tid] = m;
            m1 = shmT[tid]; s1 = shsT[tid];
            m2 = shmT[tid + off]; s2 = shsT[tid + off];
            m = fmaxf(m1, m2);
            shsT[tid] = s1 * __expf(m1 - m) + s2 * __expf(m2 - m);
            shmT[tid] = m;
        }
        __syncthreads();
    }

    if (tid == 0) {
        float lseS = shmS[0] + logf(shsS[0]);
        float lseT = shmT[0] + logf(shsT[0]);
        g_lseS[row] = lseS;
        g_lseT[row] = lseT;
        int tg = g_tgt[row];
        if (tg != IGNORE_INDEX) {
            float nll = lseS - s[tg];
            atomicAdd(&g_hard, (double)nll);
            atomicAdd(&g_nvalid, 1);
        }
    }
}

// ---------------- JSD elementwise + reduction -------------------------------
__global__ __launch_bounds__(256) void jsd_kernel() {
    const int row = blockIdx.y;
    const float lseS = g_lseS[row];
    const float lseT = g_lseT[row];
    const float* __restrict__ s = g_LS + (size_t)row * VOCAB;
    const float* __restrict__ t = g_LT + (size_t)row * VOCAB;

    float skl = 0.0f, tkl = 0.0f;
    for (int v = blockIdx.x * blockDim.x + threadIdx.x; v < VOCAB;
         v += gridDim.x * blockDim.x) {
        float lps = s[v] - lseS;
        float lpt = t[v] - lseT;
        float sp = __expf(lps);
        float tp = __expf(lpt);
        float lm = __logf(0.5f * (sp + tp));
        skl += sp * (lps - lm);
        tkl += tp * (lpt - lm);
    }

    __shared__ float sh1[256], sh2[256];
    int tid = threadIdx.x;
    sh1[tid] = skl; sh2[tid] = tkl;
    __syncthreads();
    for (int off = 128; off > 0; off >>= 1) {
        if (tid < off) {
            sh1[tid] += sh1[tid + off];
            sh2[tid] += sh2[tid + off];
        }
        __syncthreads();
    }
    if (tid == 0) {
        atomicAdd(&g_skl, (double)sh1[0]);
        atomicAdd(&g_tkl, (double)sh2[0]);
    }
}

// ---------------- finalize ---------------------------------------------------
__global__ void finalize_kernel(float* out) {
    int nv = g_nvalid > 0 ? g_nvalid : 1;
    double hard = g_hard / (double)nv;
    double jsd = 0.5 * (g_skl + g_tkl) / (double)NTOK;
    out[0] = (float)(0.5 * hard + 0.5 * jsd);
}

// ---------------- launch ------------------------------------------------------
extern "C" void kernel_launch(void* const* d_in, const int* in_sizes, int n_in,
                              void* d_out, int out_size) {
    const float* si = (const float*)d_in[0];      // (N, H/2)
    const float* ti = (const float*)d_in[1];      // (N, H)
    const float* sw = (const float*)d_in[2];      // (V, H/2)
    const float* tw = (const float*)d_in[3];      // (V, H)
    const int* tgt_raw = (const int*)d_in[4];     // int32 or int64 (detected)
    float* out = (float*)d_out;

    zero_acc_kernel<<<1, 1>>>();
    tgt_cvt_kernel<<<1, 1024>>>(tgt_raw);

    {
        int n4 = NTOK * KSTU / 4;
        cvt_kernel<<<(n4 + 255) / 256, 256>>>((const float4*)si, 0, n4);
    }
    {
        int n4 = NTOK * KTEA / 4;
        cvt_kernel<<<(n4 + 255) / 256, 256>>>((const float4*)ti, 1, n4);
    }
    {
        int n4 = VOCAB * KSTU / 4;
        cvt_kernel<<<(n4 + 255) / 256, 256>>>((const float4*)sw, 2, n4);
    }
    {
        int n4 = VOCAB * KTEA / 4;
        cvt_kernel<<<(n4 + 255) / 256, 256>>>((const float4*)tw, 3, n4);
    }

    dim3 gemm_grid(VOCAB / 128, NTOK / 128);  // (250, 16)
    gemm_kernel<0><<<gemm_grid, 256>>>();
    gemm_kernel<1><<<gemm_grid, 256>>>();

    rowstats_kernel<<<NTOK, 256>>>();
    jsd_kernel<<<dim3(8, NTOK), 256>>>();
    finalize_kernel<<<1, 1>>>(out);
}

// round 4
// speedup vs baseline: 1.2722x; 1.2722x over previous
#include <cuda_runtime.h>
#include <cuda_bf16.h>
#include <math.h>
#include <stdint.h>

#define NTOK 2048
#define VOCAB 32000
#define KSTU 1024
#define KTEA 2048
#define IGNORE_INDEX (-100)

// ---------------- scratch (device globals; no runtime allocation) -----------
__device__ __align__(16) __nv_bfloat16 g_SI[NTOK * KSTU];
__device__ __align__(16) __nv_bfloat16 g_TI[NTOK * KTEA];
__device__ __align__(16) __nv_bfloat16 g_SW[VOCAB * KSTU];
__device__ __align__(16) __nv_bfloat16 g_TW[(size_t)VOCAB * KTEA];
__device__ __align__(16) __nv_bfloat16 g_LSb[(size_t)NTOK * VOCAB];
__device__ __align__(16) __nv_bfloat16 g_LTb[(size_t)NTOK * VOCAB];
__device__ int g_tgt[NTOK];
__device__ double g_hard;
__device__ double g_skl;
__device__ double g_tkl;
__device__ int g_nvalid;

// ---------------- cp.async helpers ------------------------------------------
#define CP_ASYNC_CG(dst_u32, src_ptr) \
    asm volatile("cp.async.cg.shared.global [%0], [%1], 16;\n" ::"r"(dst_u32), \
                 "l"(src_ptr))
#define CP_ASYNC_COMMIT asm volatile("cp.async.commit_group;\n")
#define CP_ASYNC_WAIT_1 asm volatile("cp.async.wait_group 1;\n")
#define CP_ASYNC_WAIT_0 asm volatile("cp.async.wait_group 0;\n")

// ---------------- zero accumulators ----------------------------------------
__global__ void zero_acc_kernel() {
    g_hard = 0.0;
    g_skl = 0.0;
    g_tkl = 0.0;
    g_nvalid = 0;
}

// ---------------- target dtype detection + conversion -----------------------
// JAX silently downcasts int64->int32 unless x64 is enabled; handle both.
// int64 little-endian: every odd int32 word is 0 or -1 (sign ext). Random
// targets in [0,32000) can't satisfy that at all 1024 odd positions.
__global__ __launch_bounds__(1024) void tgt_cvt_kernel(const int* __restrict__ raw) {
    __shared__ int s_all64;
    int tid = threadIdx.x;
    if (tid == 0) s_all64 = 1;
    __syncthreads();
    int hw = raw[2 * tid + 1];
    if (hw != 0 && hw != -1) atomicAnd(&s_all64, 0);
    __syncthreads();
    int is64 = s_all64;
    for (int i = tid; i < NTOK; i += 1024) {
        g_tgt[i] = is64 ? raw[2 * i] : raw[i];
    }
}

// ---------------- fp32 -> bf16 convert (vectorized) ------------------------
__global__ void cvt_kernel(const float4* __restrict__ src, int which, int n4) {
    int i = blockIdx.x * blockDim.x + threadIdx.x;
    if (i >= n4) return;
    __nv_bfloat162* dst =
        which == 0 ? (__nv_bfloat162*)g_SI :
        which == 1 ? (__nv_bfloat162*)g_TI :
        which == 2 ? (__nv_bfloat162*)g_SW :
                     (__nv_bfloat162*)g_TW;
    float4 v = src[i];
    dst[2 * i + 0] = __floats2bfloat162_rn(v.x, v.y);
    dst[2 * i + 1] = __floats2bfloat162_rn(v.z, v.w);
}

// ---------------- bf16 tensor-core GEMM: C[n][v] = sum_k X[n][k] W[v][k] ----
__device__ __forceinline__ void mma16816(float c[4], const uint32_t a[4],
                                         const uint32_t b[2]) {
    asm("mma.sync.aligned.m16n8k16.row.col.f32.bf16.bf16.f32 "
        "{%0,%1,%2,%3},{%4,%5,%6,%7},{%8,%9},{%0,%1,%2,%3};"
        : "+f"(c[0]), "+f"(c[1]), "+f"(c[2]), "+f"(c[3])
        : "r"(a[0]), "r"(a[1]), "r"(a[2]), "r"(a[3]), "r"(b[0]), "r"(b[1]));
}

// Grid: x = token tile (16, fastest), y = vocab tile (250).
// A wave shares the vocab (weight) tile via L2 across token tiles, and the
// whole activation matrix (4-8MB bf16) stays L2-resident -> weights stream once.
template <int WHICH>
__global__ __launch_bounds__(256) void gemm_kernel() {
    constexpr int K = (WHICH == 0) ? KSTU : KTEA;
    constexpr int NSTAGE = K / 32;
    const __nv_bfloat16* __restrict__ A = (WHICH == 0) ? g_SI : g_TI;
    const __nv_bfloat16* __restrict__ B = (WHICH == 0) ? g_SW : g_TW;
    __nv_bfloat16* __restrict__ C = (WHICH == 0) ? g_LSb : g_LTb;

    constexpr int LDS_T = 40;  // padded row stride (elements), 80B

    __shared__ __align__(16) __nv_bfloat16 As[2][128 * LDS_T];
    __shared__ __align__(16) __nv_bfloat16 Bs[2][128 * LDS_T];

    const int m0 = blockIdx.x * 128;  // token
    const int n0 = blockIdx.y * 128;  // vocab
    const int tid = threadIdx.x;
    const int lane = tid & 31;
    const int wid = tid >> 5;
    const int warp_m = wid >> 2;   // 0..1
    const int warp_n = wid & 3;    // 0..3
    const int grp = lane >> 2;     // 0..7
    const int tq = lane & 3;       // 0..3

    // staging indices (per thread: 2 x 16B for A, 2 x 16B for B per stage)
    const int st_row0 = (tid * 8) >> 5;          // rows 0..63
    const int st_col = (tid * 8) & 31;
    const int st_row1 = st_row0 + 64;            // rows 64..127

    float acc[4][4][4];
#pragma unroll
    for (int mi = 0; mi < 4; mi++)
#pragma unroll
        for (int ni = 0; ni < 4; ni++)
#pragma unroll
            for (int r = 0; r < 4; r++) acc[mi][ni][r] = 0.0f;

    auto load_stage = [&](int ks, int buf) {
        const int k0 = ks * 32;
        uint32_t dA0 = (uint32_t)__cvta_generic_to_shared(&As[buf][st_row0 * LDS_T + st_col]);
        uint32_t dA1 = (uint32_t)__cvta_generic_to_shared(&As[buf][st_row1 * LDS_T + st_col]);
        uint32_t dB0 = (uint32_t)__cvta_generic_to_shared(&Bs[buf][st_row0 * LDS_T + st_col]);
        uint32_t dB1 = (uint32_t)__cvta_generic_to_shared(&Bs[buf][st_row1 * LDS_T + st_col]);
        CP_ASYNC_CG(dA0, &A[(size_t)(m0 + st_row0) * K + k0 + st_col]);
        CP_ASYNC_CG(dA1, &A[(size_t)(m0 + st_row1) * K + k0 + st_col]);
        CP_ASYNC_CG(dB0, &B[(size_t)(n0 + st_row0) * K + k0 + st_col]);
        CP_ASYNC_CG(dB1, &B[(size_t)(n0 + st_row1) * K + k0 + st_col]);
    };

    load_stage(0, 0);
    CP_ASYNC_COMMIT;

    for (int ks = 0; ks < NSTAGE; ks++) {
        const int buf = ks & 1;
        if (ks + 1 < NSTAGE) {
            load_stage(ks + 1, buf ^ 1);
            CP_ASYNC_COMMIT;
            CP_ASYNC_WAIT_1;
        } else {
            CP_ASYNC_WAIT_0;
        }
        __syncthreads();

        const __nv_bfloat16* __restrict__ as = As[buf];
        const __nv_bfloat16* __restrict__ bs = Bs[buf];
#pragma unroll
        for (int kk = 0; kk < 2; kk++) {
            const int kb = kk * 16;
            uint32_t a[4][4], b[4][2];
#pragma unroll
            for (int mi = 0; mi < 4; mi++) {
                int mrow = warp_m * 64 + mi * 16 + grp;
                a[mi][0] = *(const uint32_t*)&as[mrow * LDS_T + kb + tq * 2];
                a[mi][1] = *(const uint32_t*)&as[(mrow + 8) * LDS_T + kb + tq * 2];
                a[mi][2] = *(const uint32_t*)&as[mrow * LDS_T + kb + tq * 2 + 8];
                a[mi][3] = *(const uint32_t*)&as[(mrow + 8) * LDS_T + kb + tq * 2 + 8];
            }
#pragma unroll
            for (int ni = 0; ni < 4; ni++) {
                int nrow = warp_n * 32 + ni * 8 + grp;
                b[ni][0] = *(const uint32_t*)&bs[nrow * LDS_T + kb + tq * 2];
                b[ni][1] = *(const uint32_t*)&bs[nrow * LDS_T + kb + tq * 2 + 8];
            }
#pragma unroll
            for (int mi = 0; mi < 4; mi++)
#pragma unroll
                for (int ni = 0; ni < 4; ni++) mma16816(acc[mi][ni], a[mi], b[ni]);
        }
        __syncthreads();
    }

    // epilogue: bf16 logits (halves downstream memory traffic)
#pragma unroll
    for (int mi = 0; mi < 4; mi++) {
#pragma unroll
        for (int ni = 0; ni < 4; ni++) {
            int row = m0 + warp_m * 64 + mi * 16 + grp;
            int col = n0 + warp_n * 32 + ni * 8 + tq * 2;
            *(__nv_bfloat162*)&C[(size_t)row * VOCAB + col] =
                __floats2bfloat162_rn(acc[mi][ni][0], acc[mi][ni][1]);
            *(__nv_bfloat162*)&C[(size_t)(row + 8) * VOCAB + col] =
                __floats2bfloat162_rn(acc[mi][ni][2], acc[mi][ni][3]);
        }
    }
}

// -------- fused per-row logsumexp + hard CE + JSD (one block per row) -------
__global__ __launch_bounds__(256) void stats_kernel() {
    const int row = blockIdx.x;
    const __nv_bfloat16* __restrict__ s = g_LSb + (size_t)row * VOCAB;
    const __nv_bfloat16* __restrict__ t = g_LTb + (size_t)row * VOCAB;
    const int tid = threadIdx.x;
    constexpr int NCHUNK = VOCAB / 8;  // 4000 x 8 bf16

    // ---- pass 1: online logsumexp for both matrices ----
    float mS = -1e30f, sS = 0.0f, mT = -1e30f, sT = 0.0f;
    for (int c = tid; c < NCHUNK; c += 256) {
        uint4 vs = *(const uint4*)&s[c * 8];
        uint4 vt = *(const uint4*)&t[c * 8];
        const __nv_bfloat16* es = (const __nv_bfloat16*)&vs;
        const __nv_bfloat16* et = (const __nv_bfloat16*)&vt;
        float xs[8], xt[8];
        float m8S = -1e30f, m8T = -1e30f;
#pragma unroll
        for (int j = 0; j < 8; j++) {
            xs[j] = __bfloat162float(es[j]);
            xt[j] = __bfloat162float(et[j]);
            m8S = fmaxf(m8S, xs[j]);
            m8T = fmaxf(m8T, xt[j]);
        }
        float nmS = fmaxf(mS, m8S);
        float nmT = fmaxf(mT, m8T);
        float aS = 0.0f, aT = 0.0f;
#pragma unroll
        for (int j = 0; j < 8; j++) {
            aS += __expf(xs[j] - nmS);
            aT += __expf(xt[j] - nmT);
        }
        sS = sS * __expf(mS - nmS) + aS;
        sT = sT * __expf(mT - nmT) + aT;
        mS = nmS;
        mT = nmT;
    }

    __shared__ float shmS[256], shsS[256], shmT[256], shsT[256];
    shmS[tid] = mS; shsS[tid] = sS; shmT[tid] = mT; shsT[tid] = sT;
    __syncthreads();
    for (int off = 128; off > 0; off >>= 1) {
        if (tid < off) {
            float m1 = shmS[tid], s1 = shsS[tid];
            float m2 = shmS[tid + off], s2 = shsS[tid + off];
            float m = fmaxf(m1, m2);
            shsS[tid] = s1 * __expf(m1 - m) + s2 * __expf(m2 - m);
            shmS[tid] = m;
            m1 = shmT[tid]; s1 = shsT[tid];
            m2 = shmT[tid + off]; s2 = shsT[tid + off];
            m = fmaxf(m1, m2);
            shsT[tid] = s1 * __expf(m1 - m) + s2 * __expf(m2 - m);
            shmT[tid] = m;
        }
        __syncthreads();
    }

    __shared__ float sh_lseS, sh_lseT;
    if (tid == 0) {
        sh_lseS = shmS[0] + logf(shsS[0]);
        sh_lseT = shmT[0] + logf(shsT[0]);
    }
    __syncthreads();
    const float lseS = sh_lseS;
    const float lseT = sh_lseT;

    // ---- pass 2: JSD terms (row is L2-resident from pass 1) ----
    float skl = 0.0f, tkl = 0.0f;
    for (int c = tid; c < NCHUNK; c += 256) {
        uint4 vs = *(const uint4*)&s[c * 8];
        uint4 vt = *(const uint4*)&t[c * 8];
        const __nv_bfloat16* es = (const __nv_bfloat16*)&vs;
        const __nv_bfloat16* et = (const __nv_bfloat16*)&vt;
#pragma unroll
        for (int j = 0; j < 8; j++) {
            float lps = __bfloat162float(es[j]) - lseS;
            float lpt = __bfloat162float(et[j]) - lseT;
            float sp = __expf(lps);
            float tp = __expf(lpt);
            float lm = __logf(0.5f * (sp + tp));
            skl += sp * (lps - lm);
            tkl += tp * (lpt - lm);
        }
    }

    shsS[tid] = skl; shsT[tid] = tkl;
    __syncthreads();
    for (int off = 128; off > 0; off >>= 1) {
        if (tid < off) {
            shsS[tid] += shsS[tid + off];
            shsT[tid] += shsT[tid + off];
        }
        __syncthreads();
    }
    if (tid == 0) {
        atomicAdd(&g_skl, (double)shsS[0]);
        atomicAdd(&g_tkl, (double)shsT[0]);
        int tg = g_tgt[row];
        if (tg != IGNORE_INDEX) {
            float nll = lseS - __bfloat162float(s[tg]);
            atomicAdd(&g_hard, (double)nll);
            atomicAdd(&g_nvalid, 1);
        }
    }
}

// ---------------- finalize ---------------------------------------------------
__global__ void finalize_kernel(float* out) {
    int nv = g_nvalid > 0 ? g_nvalid : 1;
    double hard = g_hard / (double)nv;
    double jsd = 0.5 * (g_skl + g_tkl) / (double)NTOK;
    out[0] = (float)(0.5 * hard + 0.5 * jsd);
}

// ---------------- launch ------------------------------------------------------
extern "C" void kernel_launch(void* const* d_in, const int* in_sizes, int n_in,
                              void* d_out, int out_size) {
    const float* si = (const float*)d_in[0];      // (N, H/2)
    const float* ti = (const float*)d_in[1];      // (N, H)
    const float* sw = (const float*)d_in[2];      // (V, H/2)
    const float* tw = (const float*)d_in[3];      // (V, H)
    const int* tgt_raw = (const int*)d_in[4];     // int32 or int64 (detected)
    float* out = (float*)d_out;

    zero_acc_kernel<<<1, 1>>>();
    tgt_cvt_kernel<<<1, 1024>>>(tgt_raw);

    {
        int n4 = NTOK * KSTU / 4;
        cvt_kernel<<<(n4 + 255) / 256, 256>>>((const float4*)si, 0, n4);
    }
    {
        int n4 = NTOK * KTEA / 4;
        cvt_kernel<<<(n4 + 255) / 256, 256>>>((const float4*)ti, 1, n4);
    }
    {
        int n4 = VOCAB * KSTU / 4;
        cvt_kernel<<<(n4 + 255) / 256, 256>>>((const float4*)sw, 2, n4);
    }
    {
        int n4 = VOCAB * KTEA / 4;
        cvt_kernel<<<(n4 + 255) / 256, 256>>>((const float4*)tw, 3, n4);
    }

    dim3 gemm_grid(NTOK / 128, VOCAB / 128);  // (16, 250): token fastest
    gemm_kernel<0><<<gemm_grid, 256>>>();
    gemm_kernel<1><<<gemm_grid, 256>>>();

    stats_kernel<<<NTOK, 256>>>();
    finalize_kernel<<<1, 1>>>(out);
}